// round 6
// baseline (speedup 1.0000x reference)
#include <cuda_runtime.h>
#include <cuda_bf16.h>
#include <cstdint>

// SC2_KNN: deformed = pc1 + pred_flow; voxelize into (800,800,45) grid
// (cell 0.1 => multiply by 10.0f, matching XLA's A/const -> A*(1/const)
// rewrite where fp32(1/0.1f) == 10.0f exactly); gather nn_cell from
// full_ids (3 channels), gather nn_idx from orig_index_grid, distance to
// pc2[nn_idx]. Outputs: dist[N] then idx[N] (as float) concatenated.
//
// R6: selective L2 pinning. Full hot set (~95 MB of 128B lines) vs 126 MB
// L2 only partially retains under advisory evict_last (no carveout
// allowed). Pin a subset that comfortably fits (~71 MB: grid, pc2,
// full_ids ch0+ch1); leave ch2 on normal LRU; keep pc1/flow/out as .cs
// evict-first streaming.

#define GXD 800
#define GYD 800
#define GZD 45

__device__ __forceinline__ uint64_t evict_last_policy() {
    uint64_t pol;
    asm("createpolicy.fractional.L2::evict_last.b64 %0, 1.0;" : "=l"(pol));
    return pol;
}
__device__ __forceinline__ int ldg_hint_i32(const int* p, uint64_t pol) {
    int v;
    asm("ld.global.nc.L2::cache_hint.s32 %0, [%1], %2;"
        : "=r"(v) : "l"(p), "l"(pol));
    return v;
}
__device__ __forceinline__ float ldg_hint_f32(const float* p, uint64_t pol) {
    float v;
    asm("ld.global.nc.L2::cache_hint.f32 %0, [%1], %2;"
        : "=f"(v) : "l"(p), "l"(pol));
    return v;
}
__device__ __forceinline__ float ldg_stream_f32(const float* p) {
    float v;
    asm("ld.global.cs.nc.f32 %0, [%1];" : "=f"(v) : "l"(p));
    return v;
}
__device__ __forceinline__ void stg_stream_f32(float* p, float v) {
    asm volatile("st.global.cs.f32 [%0], %1;" :: "l"(p), "f"(v));
}

__global__ void SC2_KNN_kernel(const float* __restrict__ pc1,
                               const float* __restrict__ flow,
                               const float* __restrict__ pc2,
                               const int*   __restrict__ full_ids,
                               const int*   __restrict__ grid,
                               float*       __restrict__ out,
                               int n) {
    int i = blockIdx.x * blockDim.x + threadIdx.x;
    if (i >= n) return;

    uint64_t pol = evict_last_policy();

    // coalesced streaming point loads (evict-first: no L2 churn)
    float d0 = __fadd_rn(ldg_stream_f32(pc1 + 3 * i + 0), ldg_stream_f32(flow + 3 * i + 0));
    float d1 = __fadd_rn(ldg_stream_f32(pc1 + 3 * i + 1), ldg_stream_f32(flow + 3 * i + 1));
    float d2 = __fadd_rn(ldg_stream_f32(pc1 + 3 * i + 2), ldg_stream_f32(flow + 3 * i + 2));

    // voxelize: (d - min_range) * 10.0f, truncate, clip.
    int gx = (int)__fmul_rn(__fadd_rn(d0, 40.0f), 10.0f);
    int gy = (int)__fmul_rn(__fadd_rn(d1, 40.0f), 10.0f);
    int gz = (int)__fmul_rn(__fadd_rn(d2,  1.0f), 10.0f);
    gx = min(max(gx, 0), GXD - 1);
    gy = min(max(gy, 0), GYD - 1);
    gz = min(max(gz, 0), GZD - 1);

    // full_ids: shape (3, GX, GY, GZ). channel stride = 28,800,000 (< 2^31)
    const int CH = GXD * GYD * GZD;
    int cell = (gx * GYD + gy) * GZD + gz;
    int c0 = ldg_hint_i32(full_ids + cell,      pol);  // pinned
    int c1 = ldg_hint_i32(full_ids + CH + cell, pol);  // pinned
    int c2 = __ldg(full_ids + 2 * CH + cell);          // normal LRU

    // orig_index_grid: shape (GX, GY, GZ) — pinned
    int nn = ldg_hint_i32(grid + (c0 * GYD + c1) * GZD + c2, pol);

    // distance to pc2[nn] (hot 2.4 MB array: pinned)
    float x = ldg_hint_f32(pc2 + 3 * nn + 0, pol) - d0;
    float y = ldg_hint_f32(pc2 + 3 * nn + 1, pol) - d1;
    float z = ldg_hint_f32(pc2 + 3 * nn + 2, pol) - d2;
    float dist = sqrtf(x * x + y * y + z * z);

    stg_stream_f32(out + i,     dist);
    stg_stream_f32(out + n + i, (float)nn);
}

extern "C" void kernel_launch(void* const* d_in, const int* in_sizes, int n_in,
                              void* d_out, int out_size) {
    const float* pc1      = (const float*)d_in[0];
    const float* flow     = (const float*)d_in[1];
    const float* pc2      = (const float*)d_in[2];
    const int*   full_ids = (const int*)d_in[3];
    const int*   grid     = (const int*)d_in[4];
    float*       out      = (float*)d_out;

    int n = in_sizes[0] / 3;           // pc1 has (1, N, 3) -> 3N elements
    int threads = 256;
    int blocks  = (n + threads - 1) / threads;
    SC2_KNN_kernel<<<blocks, threads>>>(pc1, flow, pc2, full_ids, grid, out, n);
}

// round 7
// speedup vs baseline: 1.0301x; 1.0301x over previous
#include <cuda_runtime.h>
#include <cuda_bf16.h>
#include <cstdint>

// SC2_KNN: deformed = pc1 + pred_flow; voxelize into (800,800,45) grid
// (cell 0.1 => multiply by 10.0f, matching XLA's A/const -> A*(1/const)
// rewrite where fp32(1/0.1f) == 10.0f exactly); gather nn_cell from
// full_ids (3 channels), gather nn_idx from orig_index_grid, distance to
// pc2[nn_idx]. Outputs: dist[N] then idx[N] (as float) concatenated.
//
// R7: DRAM fetch-granularity probe. Cold profile shows ~128B of DRAM
// fill per random 4B gather (93 MB for 800k gathers) on the .nc texture
// path. Switch gathers to the generic ld.global path (keeping the
// evict_last cache_hint that won R5) to test whether generic loads fill
// at sector/64B granularity instead. Streams stay .cs evict-first.

#define GXD 800
#define GYD 800
#define GZD 45

__device__ __forceinline__ uint64_t evict_last_policy() {
    uint64_t pol;
    asm("createpolicy.fractional.L2::evict_last.b64 %0, 1.0;" : "=l"(pol));
    return pol;
}
// generic-path (non-.nc) gather loads with evict_last hint
__device__ __forceinline__ int ldg_gen_i32(const int* p, uint64_t pol) {
    int v;
    asm("ld.global.L2::cache_hint.s32 %0, [%1], %2;"
        : "=r"(v) : "l"(p), "l"(pol));
    return v;
}
__device__ __forceinline__ float ldg_gen_f32(const float* p, uint64_t pol) {
    float v;
    asm("ld.global.L2::cache_hint.f32 %0, [%1], %2;"
        : "=f"(v) : "l"(p), "l"(pol));
    return v;
}
__device__ __forceinline__ float ldg_stream_f32(const float* p) {
    float v;
    asm("ld.global.cs.nc.f32 %0, [%1];" : "=f"(v) : "l"(p));
    return v;
}
__device__ __forceinline__ void stg_stream_f32(float* p, float v) {
    asm volatile("st.global.cs.f32 [%0], %1;" :: "l"(p), "f"(v));
}

__global__ void SC2_KNN_kernel(const float* __restrict__ pc1,
                               const float* __restrict__ flow,
                               const float* __restrict__ pc2,
                               const int*   __restrict__ full_ids,
                               const int*   __restrict__ grid,
                               float*       __restrict__ out,
                               int n) {
    int i = blockIdx.x * blockDim.x + threadIdx.x;
    if (i >= n) return;

    uint64_t pol = evict_last_policy();

    // coalesced streaming point loads (evict-first: no L2 churn)
    float d0 = __fadd_rn(ldg_stream_f32(pc1 + 3 * i + 0), ldg_stream_f32(flow + 3 * i + 0));
    float d1 = __fadd_rn(ldg_stream_f32(pc1 + 3 * i + 1), ldg_stream_f32(flow + 3 * i + 1));
    float d2 = __fadd_rn(ldg_stream_f32(pc1 + 3 * i + 2), ldg_stream_f32(flow + 3 * i + 2));

    // voxelize: (d - min_range) * 10.0f, truncate, clip.
    int gx = (int)__fmul_rn(__fadd_rn(d0, 40.0f), 10.0f);
    int gy = (int)__fmul_rn(__fadd_rn(d1, 40.0f), 10.0f);
    int gz = (int)__fmul_rn(__fadd_rn(d2,  1.0f), 10.0f);
    gx = min(max(gx, 0), GXD - 1);
    gy = min(max(gy, 0), GYD - 1);
    gz = min(max(gz, 0), GZD - 1);

    // full_ids: shape (3, GX, GY, GZ). channel stride = 28,800,000 (< 2^31)
    const int CH = GXD * GYD * GZD;
    int cell = (gx * GYD + gy) * GZD + gz;
    int c0 = ldg_gen_i32(full_ids + cell,          pol);
    int c1 = ldg_gen_i32(full_ids + CH + cell,     pol);
    int c2 = ldg_gen_i32(full_ids + 2 * CH + cell, pol);

    // orig_index_grid: shape (GX, GY, GZ)
    int nn = ldg_gen_i32(grid + (c0 * GYD + c1) * GZD + c2, pol);

    // distance to pc2[nn] (hot 2.4 MB array)
    float x = ldg_gen_f32(pc2 + 3 * nn + 0, pol) - d0;
    float y = ldg_gen_f32(pc2 + 3 * nn + 1, pol) - d1;
    float z = ldg_gen_f32(pc2 + 3 * nn + 2, pol) - d2;
    float dist = sqrtf(x * x + y * y + z * z);

    stg_stream_f32(out + i,     dist);
    stg_stream_f32(out + n + i, (float)nn);
}

extern "C" void kernel_launch(void* const* d_in, const int* in_sizes, int n_in,
                              void* d_out, int out_size) {
    const float* pc1      = (const float*)d_in[0];
    const float* flow     = (const float*)d_in[1];
    const float* pc2      = (const float*)d_in[2];
    const int*   full_ids = (const int*)d_in[3];
    const int*   grid     = (const int*)d_in[4];
    float*       out      = (float*)d_out;

    int n = in_sizes[0] / 3;           // pc1 has (1, N, 3) -> 3N elements
    int threads = 256;
    int blocks  = (n + threads - 1) / threads;
    SC2_KNN_kernel<<<blocks, threads>>>(pc1, flow, pc2, full_ids, grid, out, n);
}